// round 17
// baseline (speedup 1.0000x reference)
#include <cuda_runtime.h>
#include <cuda_fp16.h>
#include <cstdint>

// y = x @ W^T + bias, B=K=N=512 fp32.  LNS reference == plain fp32 matmul.
// Single-term fp16 HMMA (rel_err ~2.9e-4, budget 1e-3), fp32 accumulate.
// Single-phase: full K=512 in smem, ONE barrier, then 32 ldsm+mma steps.
// This round: warp-contiguous producer mapping. Each warp loads whole rows
// (32 lanes = 32 consecutive float4 = 512B contiguous per LDG) so every
// warp-LDG touches 4 fully-used lines instead of 8 half-used ones ->
// L1tex wavefronts for the load phase halve (the dominant serial term).

constexpr int KDIM = 512;
constexpr int NDIM = 512;
constexpr int BDIM = 512;

constexpr int BM = 64;
constexpr int BN = 32;
constexpr int NTH = 256;                 // 8 warps, 4x2 grid of 16x16 tiles

// smem row: 512 fp16 = 1024B + 16B pad = 1040B (260 words; 260 mod 32 = 4
// -> 8-row ldmatrix phases hit disjoint bank quads).
constexpr int ROWB = 1040;
constexpr int A_OFF = 0;
constexpr int B_OFF = BM * ROWB;              // 66560
constexpr int SMEM_TOTAL = B_OFF + BN * ROWB; // 99840 (1 CTA/SM)

__device__ __forceinline__ uint32_t smem_u32(const void* p) {
    uint32_t a;
    asm("{ .reg .u64 t; cvta.to.shared.u64 t, %1; cvt.u32.u64 %0, t; }"
        : "=r"(a) : "l"(p));
    return a;
}

__device__ __forceinline__ void ldsm_x4(uint32_t* r, uint32_t addr) {
    asm volatile("ldmatrix.sync.aligned.m8n8.x4.shared.b16 {%0,%1,%2,%3}, [%4];"
                 : "=r"(r[0]), "=r"(r[1]), "=r"(r[2]), "=r"(r[3]) : "r"(addr));
}

__device__ __forceinline__ void mma16816(float* c, const uint32_t* a,
                                         uint32_t b0, uint32_t b1) {
    asm volatile(
        "mma.sync.aligned.m16n8k16.row.col.f32.f16.f16.f32 "
        "{%0,%1,%2,%3}, {%4,%5,%6,%7}, {%8,%9}, {%0,%1,%2,%3};"
        : "+f"(c[0]), "+f"(c[1]), "+f"(c[2]), "+f"(c[3])
        : "r"(a[0]), "r"(a[1]), "r"(a[2]), "r"(a[3]), "r"(b0), "r"(b1));
}

// float4 -> 4 fp16 (8 bytes) store.
__device__ __forceinline__ void cvt_sts(char* smem, uint32_t byte_off, float4 v) {
    __half2 h0 = __floats2half2_rn(v.x, v.y);
    __half2 h1 = __floats2half2_rn(v.z, v.w);
    *reinterpret_cast<uint2*>(smem + byte_off) =
        make_uint2(*reinterpret_cast<uint32_t*>(&h0),
                   *reinterpret_cast<uint32_t*>(&h1));
}

__global__ __launch_bounds__(NTH, 1)
void lns_linear_kernel(const float* __restrict__ X,
                       const float* __restrict__ W,
                       const float* __restrict__ bias,
                       float* __restrict__ Y)
{
    extern __shared__ char smem[];
    const uint32_t sb = smem_u32(smem);
    const int tid = threadIdx.x;
    const int wid = tid >> 5;
    const int lid = tid & 31;
    const int wm = wid >> 1;              // 0..3  (m tile of 16)
    const int wn = wid & 1;               // 0..1  (n tile of 16)
    const int block_m = blockIdx.y * BM;
    const int block_n = blockIdx.x * BN;

    // ---- single-phase producer, warp-contiguous ----
    // A: warp w loads rows [8w, 8w+8); per row 4 warp-LDGs, lane covers
    //    float4 slot j*32+lid  -> 512B contiguous per warp-LDG.
    // B: warp w loads rows [4w, 4w+4), same inner mapping.
    {
        const int a_row0 = wid * 8;
        const float* Arow = X + (block_m + a_row0) * KDIM;
        #pragma unroll
        for (int r = 0; r < 8; ++r) {
            #pragma unroll
            for (int j = 0; j < 4; ++j) {
                const int slot = j * 32 + lid;
                float4 v = *reinterpret_cast<const float4*>(Arow + r * KDIM + slot * 4);
                cvt_sts(smem, A_OFF + (uint32_t)((a_row0 + r) * ROWB + slot * 8), v);
            }
        }
        const int b_row0 = wid * 4;
        const float* Brow = W + (block_n + b_row0) * KDIM;
        #pragma unroll
        for (int r = 0; r < 4; ++r) {
            #pragma unroll
            for (int j = 0; j < 4; ++j) {
                const int slot = j * 32 + lid;
                float4 v = *reinterpret_cast<const float4*>(Brow + r * KDIM + slot * 4);
                cvt_sts(smem, B_OFF + (uint32_t)((b_row0 + r) * ROWB + slot * 8), v);
            }
        }
    }
    __syncthreads();   // the ONLY barrier

    // ---- ldmatrix lane addressing (byte offsets within tile) ----
    const uint32_t a_ld = (uint32_t)((wm * 16 + (lid & 15)) * ROWB + (lid >> 4) * 16);
    const uint32_t b_ld = (uint32_t)((wn * 16 + ((lid & 7) | ((lid >> 4) << 3))) * ROWB
                                     + (((lid >> 3) & 1) * 16));

    // 4 independent accumulator chains: {even,odd k-step} x {n8 block 0,1}
    float c0[2][4] = {};
    float c1[2][4] = {};

    #pragma unroll
    for (int s = 0; s < KDIM / 16; ++s) {   // 32 k-steps, no barriers
        const int p = s & 1;
        uint32_t a[4], b[4];
        ldsm_x4(a, sb + A_OFF + a_ld + s * 32);
        ldsm_x4(b, sb + B_OFF + b_ld + s * 32);
        mma16816(c0[p], a, b[0], b[1]);
        mma16816(c1[p], a, b[2], b[3]);
    }

    // ---- epilogue: merge chains, add bias, store ----
    const int row0 = block_m + wm * 16 + (lid >> 2);
    const int coln = block_n + wn * 16 + 2 * (lid & 3);
    float f0[4], f1[4];
    #pragma unroll
    for (int j = 0; j < 4; ++j) {
        f0[j] = c0[0][j] + c0[1][j];
        f1[j] = c1[0][j] + c1[1][j];
    }
    #pragma unroll
    for (int j = 0; j < 2; ++j) {
        const float* cc = j ? f1 : f0;
        const int n = coln + j * 8;
        float2 bv = *reinterpret_cast<const float2*>(bias + n);
        *reinterpret_cast<float2*>(Y + row0 * NDIM + n) =
            make_float2(cc[0] + bv.x, cc[1] + bv.y);
        *reinterpret_cast<float2*>(Y + (row0 + 8) * NDIM + n) =
            make_float2(cc[2] + bv.x, cc[3] + bv.y);
    }
}

extern "C" void kernel_launch(void* const* d_in, const int* in_sizes, int n_in,
                              void* d_out, int out_size)
{
    const float* x    = (const float*)d_in[0];   // [512, 512]
    const float* w    = (const float*)d_in[1];   // [512, 512] (N, K)
    const float* bias = (const float*)d_in[2];   // [512]
    float* y = (float*)d_out;                    // [512, 512]

    cudaFuncSetAttribute(lns_linear_kernel,
                         cudaFuncAttributeMaxDynamicSharedMemorySize, SMEM_TOTAL);
    dim3 grid(NDIM / BN, BDIM / BM);             // (16, 8) = 128 CTAs, one wave
    lns_linear_kernel<<<grid, NTH, SMEM_TOTAL>>>(x, w, bias, y);
}